// round 15
// baseline (speedup 1.0000x reference)
#include <cuda_runtime.h>
#include <stdint.h>
#include <math.h>

// Problem constants
#define BB 8
#define HH 640
#define WW 640
#define NPIX (HH*WW)          // 409600 pixels per sample
#define NF4  (NPIX/4)         // 102400 float4s per sample
#define BPS 74                // blocks per sample -> 8*74 = 592 = 148 SMs * 4
#define NBLK (BB*BPS)         // 592 blocks: one wave at 4 blocks/SM (smem-capped 5)
#define NT 128                // 4 warps
#define NW (NT/32)
#define NSTR 10               // input streams per pixel group
#define STAGES 2
#define HBINS 2048

// -------- device scratch: per-block partial rows (plain stores, no init needed) --------
// layout per block: [cls, pos, tot, posc, norm, ang, angc, pad]
__device__ double g_part[NBLK][8];
__device__ unsigned int g_ticket = 0;   // self-resetting; 0 at module load

__device__ __forceinline__ double warp_red(double v) {
    #pragma unroll
    for (int o = 16; o > 0; o >>= 1) v += __shfl_down_sync(0xffffffffu, v, o);
    return v;
}

__device__ __forceinline__ float f_rsqrt(float x) {
    float r; asm("rsqrt.approx.f32 %0, %1;" : "=f"(r) : "f"(x)); return r;
}

__device__ __forceinline__ uint32_t smem_u32(const void* p) {
    uint32_t a;
    asm("{ .reg .u64 t; cvta.to.shared.u64 t, %1; cvt.u32.u64 %0, t; }" : "=r"(a) : "l"(p));
    return a;
}
__device__ __forceinline__ void cp16(uint32_t saddr, const void* g) {
    asm volatile("cp.async.cg.shared.global [%0], [%1], 16;" :: "r"(saddr), "l"(g) : "memory");
}
__device__ __forceinline__ void cp_commit() {
    asm volatile("cp.async.commit_group;" ::: "memory");
}
template<int N> __device__ __forceinline__ void cp_wait() {
    asm volatile("cp.async.wait_group %0;" :: "n"(N) : "memory");
}

// transformed key: pos pixels -> 0 (sorts last), neg -> bits(pre)+1 (monotone, pre>=0)
__device__ __forceinline__ unsigned key_of(float d1, float dfv, float tm) {
    float diff = d1 - dfv;
    float pre  = diff * diff * tm;
    return (dfv >= 1e-3f) ? 0u : (__float_as_uint(pre) + 1u);
}

// ---------------- single fused kernel ----------------
__global__ void __launch_bounds__(NT) k_all(
    const float* __restrict__ fy,      // [B,4,H,W]
    const float* __restrict__ tmask,   // [B,H,W] float (values 0.0/1.0)
    const int*   __restrict__ trm,     // [B,H,W] int
    const float* __restrict__ distf,   // [B,H,W]
    const float* __restrict__ dirf,    // [B,2,H,W]
    const float* __restrict__ wm,      // [B,H,W]
    float* __restrict__ out)
{
    const int s   = blockIdx.x / BPS;
    const int blk = blockIdx.x % BPS;
    const int tid = threadIdx.x;
    const int wid = tid >> 5, lid = tid & 31;

    // pipeline buffer aliased (union) with finalize scratch
    __shared__ union ShU {
        float4 pipe[STAGES][NSTR][NT];                 // 40 KB
        struct {
            double sh[NW][7];
            double sGlob[NW][4];
            double sPos[BB], sTot[BB], sCnt[BB], sPersample[BB];
            long long sK[BB];
            int  sNeed[BB];
            int  sAnyNeed;
            unsigned sHist[HBINS];
            unsigned sPrefix;
            long long sKrem;
            double sGt[NW];
            unsigned long long sAb[NW];
        } fin;
    } sm;

    const int beg = (int)(((long long)blk       * NF4) / BPS);
    const int end = (int)(((long long)(blk + 1) * NF4) / BPS);
    const int nIter = (end - beg + NT - 1) / NT;

    float cls_a = 0.f, pos_a = 0.f, tot_a = 0.f, norm_a = 0.f, ang_a = 0.f, angc_a = 0.f;
    int posc = 0;

    // ======== phase 1: cp.async-pipelined fused pass ========
    {
        const float4* gs[NSTR];
        gs[0] = (const float4*)(fy + ((size_t)s*4 + 0) * NPIX);
        gs[1] = (const float4*)(fy + ((size_t)s*4 + 1) * NPIX);
        gs[2] = (const float4*)(fy + ((size_t)s*4 + 2) * NPIX);
        gs[3] = (const float4*)(fy + ((size_t)s*4 + 3) * NPIX);
        gs[4] = (const float4*)(dirf + ((size_t)s*2 + 0) * NPIX);
        gs[5] = (const float4*)(dirf + ((size_t)s*2 + 1) * NPIX);
        gs[6] = (const float4*)(tmask + (size_t)s * NPIX);
        gs[7] = (const float4*)(distf + (size_t)s * NPIX);
        gs[8] = (const float4*)(wm    + (size_t)s * NPIX);
        gs[9] = (const float4*)(trm   + (size_t)s * NPIX);

        const uint32_t pbase = smem_u32(&sm.pipe[0][0][0]);

        // issue stage `st` for iteration `it` (per-thread; producer == consumer)
        auto issue = [&](int it, int st) {
            int i4 = beg + it * NT + tid;
            if (i4 < end) {
                uint32_t sb = pbase + (uint32_t)(st * NSTR * NT + tid) * 16u;
                #pragma unroll
                for (int k = 0; k < NSTR; k++)
                    cp16(sb + (uint32_t)(k * NT) * 16u, gs[k] + i4);
            }
        };

        issue(0, 0);
        cp_commit();

        for (int it = 0; it < nIter; it++) {
            if (it + 1 < nIter) issue(it + 1, (it + 1) & 1);
            cp_commit();
            cp_wait<1>();          // stage `it` landed (own copies)

            int i4 = beg + it * NT + tid;
            if (i4 < end) {
                const int st = it & 1;
                float4 p4 = sm.pipe[st][0][tid];
                float4 q4 = sm.pipe[st][1][tid];
                float4 x4 = sm.pipe[st][2][tid];
                float4 y4 = sm.pipe[st][3][tid];
                float4 g1 = sm.pipe[st][4][tid];
                float4 g2 = sm.pipe[st][5][tid];
                float4 t4 = sm.pipe[st][6][tid];
                float4 d4 = sm.pipe[st][7][tid];
                float4 w4 = sm.pipe[st][8][tid];
                int4   r4 = *(const int4*)&sm.pipe[st][9][tid];

                #pragma unroll
                for (int e = 0; e < 4; e++) {
                    float p   = ((const float*)&p4)[e];
                    float d1  = ((const float*)&q4)[e];
                    float px  = ((const float*)&x4)[e];
                    float py  = ((const float*)&y4)[e];
                    float gx  = ((const float*)&g1)[e];
                    float gy  = ((const float*)&g2)[e];
                    float tm  = ((const float*)&t4)[e];
                    float dfv = ((const float*)&d4)[e];
                    float w   = ((const float*)&w4)[e];
                    int   tr  = ((const int*)&r4)[e];
                    bool  trp = (tr > 0);

                    // cls: masked BCE
                    float pc  = fminf(fmaxf(p, 1e-7f), 1.0f - 1e-7f);
                    float arg = trp ? pc : (1.0f - pc);
                    cls_a -= __logf(arg) * tm;

                    // distance pre-loss
                    float diff = d1 - dfv;
                    float pre  = diff * diff * tm;
                    bool  pos  = (dfv >= 1e-3f);
                    tot_a += pre;
                    pos_a += pos ? pre : 0.0f;
                    posc  += pos ? 1 : 0;

                    // flux norm (rsqrt form of rcp(gl+1e-6))
                    float sg  = gx*gx + gy*gy;
                    float isg = f_rsqrt(sg + 1e-12f);
                    float gtx = gx * isg, gty = gy * isg;
                    float ex = px - gtx, ey = py - gty;
                    norm_a += w * (ex*ex + ey*ey) * tm;   // 0.5 hoisted

                    // angle: eps terms cancel -> cos = p.g / (|p||g|)
                    float amask = trp ? tm : 0.0f;
                    float sp    = px*px + py*py;
                    float dotpg = px*gx + py*gy;
                    float cosv  = dotpg * f_rsqrt(fmaxf(sp * sg, 1e-40f));
                    ang_a  += amask * (1.0f - cosv);
                    angc_a += amask;
                }
            }
        }
        cp_wait<0>();
    }
    __syncthreads();   // all async copies landed; pipe buffer dead -> fin alias safe

    // block reduction -> per-block partial row
    {
        double v0 = warp_red((double)cls_a);
        double v1 = warp_red((double)pos_a);
        double v2 = warp_red((double)tot_a);
        double v3 = warp_red((double)posc);
        double v4 = warp_red((double)norm_a);
        double v5 = warp_red((double)ang_a);
        double v6 = warp_red((double)angc_a);
        if (lid == 0) {
            sm.fin.sh[wid][0]=v0; sm.fin.sh[wid][1]=v1; sm.fin.sh[wid][2]=v2;
            sm.fin.sh[wid][3]=v3; sm.fin.sh[wid][4]=v4; sm.fin.sh[wid][5]=v5;
            sm.fin.sh[wid][6]=v6;
        }
        __syncthreads();
        if (tid == 0) {
            double t[7] = {0,0,0,0,0,0,0};
            #pragma unroll
            for (int k = 0; k < NW; k++)
                #pragma unroll
                for (int q = 0; q < 7; q++) t[q] += sm.fin.sh[k][q];
            #pragma unroll
            for (int q = 0; q < 7; q++) g_part[blockIdx.x][q] = t[q];
            g_part[blockIdx.x][7] = 0.0;
        }
    }

    // ======== phase 2: last block finalizes ========
    __shared__ bool amLast;
    __threadfence();
    if (tid == 0) {
        unsigned t = atomicAdd(&g_ticket, 1u);
        amLast = (t == (unsigned)(NBLK - 1));
        if (amLast) g_ticket = 0u;           // self-reset for graph replay
    }
    __syncthreads();
    if (!amLast) return;

    // --- finalize (single block, 4 warps) ---
    {
        double c = 0, nrm = 0, an = 0, anc = 0;
        for (int i = tid; i < NBLK; i += NT) {
            const double* r = g_part[i];
            c += r[0]; nrm += r[4]; an += r[5]; anc += r[6];
        }
        c = warp_red(c); nrm = warp_red(nrm); an = warp_red(an); anc = warp_red(anc);
        if (lid == 0) { sm.fin.sGlob[wid][0]=c; sm.fin.sGlob[wid][1]=nrm;
                        sm.fin.sGlob[wid][2]=an; sm.fin.sGlob[wid][3]=anc; }

        // per-sample sums: warp w handles samples w and w+4
        #pragma unroll
        for (int rep = 0; rep < 2; rep++) {
            int ss = wid + rep * NW;
            double ps = 0, ts = 0, pc = 0;
            for (int i = lid; i < BPS; i += 32) {
                const double* r = g_part[ss * BPS + i];
                ps += r[1]; ts += r[2]; pc += r[3];
            }
            ps = warp_red(ps); ts = warp_red(ts); pc = warp_red(pc);
            if (lid == 0) { sm.fin.sPos[ss] = ps; sm.fin.sTot[ss] = ts; sm.fin.sCnt[ss] = pc; }
        }
        __syncthreads();
    }

    if (tid == 0) sm.fin.sAnyNeed = 0;
    __syncthreads();
    if (tid < BB) {
        int ss = tid;
        long long npos = (long long)(sm.fin.sCnt[ss] + 0.5);
        long long nneg = (long long)NPIX - npos;
        double posi = 0.0, persample = 0.0;
        int need = 0; long long k = 0;
        double negsum_all = sm.fin.sTot[ss] - sm.fin.sPos[ss];
        if (npos > 0) {
            k = 3 * npos; if (nneg < k) k = nneg;
            posi = sm.fin.sPos[ss] / (double)(npos > 1 ? npos : 1);
            if (k <= 0)          persample = posi;
            else if (k == nneg)  persample = posi + negsum_all / (double)k;
            else                 { need = 1; atomicAdd(&sm.fin.sAnyNeed, 1); }
        } else {
            k = 100; need = 1; posi = 0.0; atomicAdd(&sm.fin.sAnyNeed, 1);
        }
        sm.fin.sPersample[ss] = persample;
        sm.fin.sNeed[ss] = need;
        sm.fin.sK[ss] = k;
        sm.fin.sPos[ss] = posi;
    }
    __syncthreads();

    // rare exact top-k path: 3-level radix select (11/11/10 bits), tie-exact
    if (sm.fin.sAnyNeed) {
        for (int ss = 0; ss < BB; ss++) {
            if (!sm.fin.sNeed[ss]) continue;
            const float* ch1 = fy + ((size_t)ss*4 + 1) * NPIX;
            const float* tmp = tmask + (size_t)ss * NPIX;
            const float* dfp = distf + (size_t)ss * NPIX;
            if (tid == 0) { sm.fin.sKrem = sm.fin.sK[ss]; sm.fin.sPrefix = 0u; }
            __syncthreads();

            const int lvBits[3]  = {11, 11, 10};
            const int lvShift[3] = {21, 10, 0};
            int nbDone = 0;
            for (int lv = 0; lv < 3; lv++) {
                for (int i = tid; i < HBINS; i += NT) sm.fin.sHist[i] = 0u;
                __syncthreads();
                unsigned pmask = nbDone ? (0xffffffffu << (32 - nbDone)) : 0u;
                unsigned pref  = sm.fin.sPrefix;
                for (int i = tid; i < NPIX; i += NT) {
                    unsigned u = key_of(__ldg(ch1+i), __ldg(dfp+i), __ldg(tmp+i));
                    if ((u & pmask) == pref)
                        atomicAdd(&sm.fin.sHist[(u >> lvShift[lv]) & ((1u << lvBits[lv]) - 1u)], 1u);
                }
                __syncthreads();
                if (tid == 0) {
                    long long krem = sm.fin.sKrem, above = 0;
                    int nb = (1 << lvBits[lv]), bsel = 0;
                    for (int b = nb - 1; b >= 0; b--) {
                        long long cc = (long long)sm.fin.sHist[b];
                        if (above + cc >= krem) { bsel = b; break; }
                        above += cc;
                    }
                    sm.fin.sKrem = krem - above;
                    sm.fin.sPrefix = sm.fin.sPrefix | ((unsigned)bsel << lvShift[lv]);
                }
                __syncthreads();
                nbDone += lvBits[lv];
            }
            unsigned pivot_u = sm.fin.sPrefix;
            double gt_local = 0.0; unsigned long long ab_local = 0ull;
            for (int i = tid; i < NPIX; i += NT) {
                float d1 = __ldg(ch1+i), dfv = __ldg(dfp+i), t = __ldg(tmp+i);
                float diff = d1 - dfv;
                float pre  = diff * diff * t;
                unsigned u = (dfv >= 1e-3f) ? 0u : (__float_as_uint(pre) + 1u);
                if (u > pivot_u) { gt_local += (double)pre; ab_local++; }
            }
            double gv = warp_red(gt_local);
            double av = warp_red((double)ab_local);
            if (lid == 0) { sm.fin.sGt[wid] = gv; sm.fin.sAb[wid] = (unsigned long long)(av + 0.5); }
            __syncthreads();
            if (tid == 0) {
                double gts = 0; long long above = 0;
                for (int w = 0; w < NW; w++) { gts += sm.fin.sGt[w]; above += (long long)sm.fin.sAb[w]; }
                long long k = sm.fin.sK[ss];
                long long take = k - above;
                float pivotf = __uint_as_float(pivot_u - 1u);
                double negsum = gts + (double)take * (double)pivotf;
                long long kd = k < 1 ? 1 : k;
                sm.fin.sPersample[ss] = sm.fin.sPos[ss] + negsum / (double)kd;
            }
            __syncthreads();
        }
    }

    // combine
    if (tid == 0) {
        double cls = 0, nr = 0, ag = 0, agc = 0;
        for (int w = 0; w < NW; w++) {
            cls += sm.fin.sGlob[w][0]; nr += sm.fin.sGlob[w][1];
            ag  += sm.fin.sGlob[w][2]; agc += sm.fin.sGlob[w][3];
        }
        double dis = 0;
        for (int ss = 0; ss < BB; ss++) dis += sm.fin.sPersample[ss];
        dis /= (double)BB;
        cls /= (double)BB * (double)NPIX;
        nr  = nr * 0.5 / ((double)BB * (double)HH);   // hoisted 0.5; .sum(-1).mean()
        long long ac = (long long)(agc + 0.5); if (ac < 1) ac = 1;
        ag /= (double)ac;
        out[0] = (float)(cls + 3.0 * dis + 0.5 * (nr + ag));
    }
}

// ---------------- launcher: one kernel ----------------
extern "C" void kernel_launch(void* const* d_in, const int* in_sizes, int n_in,
                              void* d_out, int out_size) {
    const float* fy    = (const float*)d_in[0];
    const float* tmask = (const float*)d_in[1];
    const int*   trm   = (const int*)  d_in[2];
    const float* distf = (const float*)d_in[3];
    const float* dirf  = (const float*)d_in[4];
    const float* wm    = (const float*)d_in[5];
    float* out = (float*)d_out;

    k_all<<<NBLK, NT>>>(fy, tmask, trm, distf, dirf, wm, out);
}